// round 2
// baseline (speedup 1.0000x reference)
#include <cuda_runtime.h>
#include <cuda_bf16.h>
#include <stdint.h>

// Problem constants (shapes fixed by dataset; sizes re-derived at launch).
#define MAX_NODES 100000
#define OUT_CH    32

// Scratch (no cudaMalloc allowed): transposed weights Wt[N, 32] and row-min.
__device__ float g_Wt[MAX_NODES * OUT_CH];   // 12.8 MB
__device__ int   g_rowmin;

// ---------------------------------------------------------------------------
// Kernel 1: out[n, c] = b[c] for all n; reset g_rowmin.
// ---------------------------------------------------------------------------
__global__ void init_out_kernel(float* __restrict__ out, const float* __restrict__ b,
                                int total) {
    int i = blockIdx.x * blockDim.x + threadIdx.x;
    if (i == 0) g_rowmin = 0x7fffffff;
    if (i < total) {
        out[i] = __ldg(&b[i & (OUT_CH - 1)]);
    }
}

// ---------------------------------------------------------------------------
// Kernel 2: g_rowmin = min over rows (edge_index[0, :]). int32 data.
// ---------------------------------------------------------------------------
__global__ void rowmin_kernel(const int* __restrict__ rows, int E) {
    int i = blockIdx.x * blockDim.x + threadIdx.x;
    int stride = gridDim.x * blockDim.x;
    int m = 0x7fffffff;
    for (; i < E; i += stride) {
        m = min(m, __ldg(&rows[i]));
    }
    #pragma unroll
    for (int off = 16; off > 0; off >>= 1)
        m = min(m, __shfl_xor_sync(0xffffffffu, m, off));
    if ((threadIdx.x & 31) == 0)
        atomicMin(&g_rowmin, m);
}

// ---------------------------------------------------------------------------
// Kernel 3: transpose W[32, N] -> Wt[N, 32]. Reads coalesced along N; each
// thread writes its own 128B row via 8x float4.
// ---------------------------------------------------------------------------
__global__ void transpose_kernel(const float* __restrict__ W, int N) {
    int n = blockIdx.x * blockDim.x + threadIdx.x;
    if (n >= N) return;
    float v[OUT_CH];
    #pragma unroll
    for (int c = 0; c < OUT_CH; c++)
        v[c] = __ldg(&W[(size_t)c * N + n]);
    float4* dst = reinterpret_cast<float4*>(&g_Wt[(size_t)n * OUT_CH]);
    #pragma unroll
    for (int j = 0; j < OUT_CH / 4; j++)
        dst[j] = make_float4(v[4*j+0], v[4*j+1], v[4*j+2], v[4*j+3]);
}

// ---------------------------------------------------------------------------
// Kernel 4: scatter. 8 threads per edge; thread t handles channels [4t, 4t+4)
// with one float4 gather from Wt (L2-resident) + one red.global.add.v4.f32.
// ---------------------------------------------------------------------------
__global__ void scatter_kernel(const int* __restrict__ ei, int E, int N,
                               float* __restrict__ out) {
    long long gtid = (long long)blockIdx.x * blockDim.x + threadIdx.x;
    long long e = gtid >> 3;
    int t = (int)(gtid & 7);
    if (e >= E) return;
    int minr = g_rowmin;
    int row = __ldg(&ei[e]) - minr;
    int col = __ldg(&ei[E + e]);
    // Guards: segment_sum drops OOB rows; col guard is defensive (prevents
    // crashes if dtype/order assumptions are wrong — shows up as rel_err).
    if ((unsigned)row >= (unsigned)N) return;
    if ((unsigned)col >= (unsigned)N) return;

    const float4* src = reinterpret_cast<const float4*>(&g_Wt[(size_t)col * OUT_CH]);
    float4 v = __ldg(&src[t]);
    float* dst = &out[(size_t)row * OUT_CH + t * 4];
    asm volatile("red.global.add.v4.f32 [%0], {%1, %2, %3, %4};"
                 :: "l"(dst), "f"(v.x), "f"(v.y), "f"(v.z), "f"(v.w)
                 : "memory");
}

// ---------------------------------------------------------------------------
extern "C" void kernel_launch(void* const* d_in, const int* in_sizes, int n_in,
                              void* d_out, int out_size) {
    const int*   ei = (const int*)d_in[0];     // [2, E] (int64 in ref, int32 in harness)
    const float* W  = (const float*)d_in[1];   // [32, N]
    const float* b  = (const float*)d_in[2];   // [32]
    float* out = (float*)d_out;                // [N, 32]

    int E = in_sizes[0] / 2;
    int N = in_sizes[1] / OUT_CH;
    int total_out = out_size;

    // 1) init out = b (broadcast), reset min
    {
        int threads = 256;
        int blocks = (total_out + threads - 1) / threads;
        init_out_kernel<<<blocks, threads>>>(out, b, total_out);
    }
    // 2) row min
    {
        rowmin_kernel<<<1024, 256>>>(ei, E);
    }
    // 3) transpose W -> Wt
    {
        int threads = 256;
        int blocks = (N + threads - 1) / threads;
        transpose_kernel<<<blocks, threads>>>(W, N);
    }
    // 4) scatter-add
    {
        long long work = (long long)E * 8;
        int threads = 256;
        int blocks = (int)((work + threads - 1) / threads);
        scatter_kernel<<<blocks, threads>>>(ei, E, N, out);
    }
}